// round 11
// baseline (speedup 1.0000x reference)
#include <cuda_runtime.h>
#include <cuda_fp16.h>
#include <cstdint>
#include <math_constants.h>

#define NAG 1024
#define THREADS 256
#define GRID_MAIN 148
#define NUNITS 1024          // 16 i-tiles x 64 j-subchunks(16 j each)

__device__ __half g_Uh[NAG * 128];
__device__ __half g_Qh[NAG * 128];
__device__ unsigned int g_amax[NAG * 64];   // monotone-mapped f32 max keys

// ---------------- helpers ----------------
__device__ __forceinline__ uint32_t pack_h2(float lo, float hi) {
    uint32_t r;
    asm("cvt.rn.f16x2.f32 %0, %1, %2;" : "=r"(r) : "f"(hi), "f"(lo));
    return r;
}
__device__ __forceinline__ uint32_t h2u(__half2 h) {
    return *reinterpret_cast<uint32_t*>(&h);
}
// order-preserving f32 -> u32 (all finite keys > 0, so init 0 == -inf)
__device__ __forceinline__ unsigned int fkey(float f) {
    unsigned int b = __float_as_uint(f);
    return (b & 0x80000000u) ? ~b : (b | 0x80000000u);
}
__device__ __forceinline__ float funkey(unsigned int k) {
    return (k & 0x80000000u) ? __uint_as_float(k ^ 0x80000000u)
                             : __uint_as_float(~k);
}

// mma.sync m16n8k16 f16, f32 accum
__device__ __forceinline__ void mma_f16(float* d,
                                        uint32_t a0, uint32_t a1, uint32_t a2, uint32_t a3,
                                        uint32_t b0, uint32_t b1) {
    asm volatile(
        "mma.sync.aligned.m16n8k16.row.col.f32.f16.f16.f32 "
        "{%0,%1,%2,%3}, {%4,%5,%6,%7}, {%8,%9}, {%0,%1,%2,%3};"
        : "+f"(d[0]), "+f"(d[1]), "+f"(d[2]), "+f"(d[3])
        : "r"(a0), "r"(a1), "r"(a2), "r"(a3), "r"(b0), "r"(b1));
}

// ---------------- Kernel 1: precompute U, Q (fp16) + zero amax ----------------
__global__ void precompute_kernel(const float* __restrict__ hidden,
                                  const float* __restrict__ track,
                                  const float* __restrict__ W_e,
                                  const float* __restrict__ b_e,
                                  const float* __restrict__ W1,
                                  const float* __restrict__ b1) {
    __shared__ float sh[64];
    __shared__ float sP[16];
    int a = blockIdx.x;
    int m = threadIdx.x;  // 0..127
    if (m < 64) {
        sh[m] = hidden[a * 64 + m];
        g_amax[a * 64 + m] = 0u;   // reset max keys every launch
    }
    if (m < 16) {
        float e0 = track[a * 16 + 14];
        float e1 = track[a * 16 + 15];
        sP[m] = e0 * W_e[m] + e1 * W_e[16 + m];
    }
    __syncthreads();
    float acc = b1[m];
#pragma unroll 8
    for (int h = 0; h < 64; h++) acc = fmaf(sh[h], W1[h * 128 + m], acc);
    float q = 0.f;
#pragma unroll
    for (int e = 0; e < 16; e++) {
        float w = W1[(64 + e) * 128 + m];
        q = fmaf(sP[e], w, q);
        acc = fmaf(b_e[e], w, acc);
    }
    g_Qh[a * 128 + m] = __float2half_rn(q);
    g_Uh[a * 128 + m] = __float2half_rn(acc + q);
}

// ---------------- Kernel 2: persistent relu(U[j]-Q[i]) @ W2, atomic max over j ----------------
// 148 CTAs, 8 warps = 4 i-groups(16 rows) x 2 n-halves(32 cols); unit = (i-tile 64, 16 j's)
__global__ void __launch_bounds__(THREADS, 1)
main_kernel(const float* __restrict__ W2) {
    const int tid  = threadIdx.x;
    const int wid  = tid >> 5;
    const int lane = tid & 31;
    const int g = lane >> 2;
    const int c = lane & 3;
    const int mg = wid >> 1;
    const int nh = wid & 1;

    // W2 fragments (f16x2), invariant.
    uint32_t Wf[4][8][2];
#pragma unroll
    for (int nt = 0; nt < 4; nt++) {
        const int n = nh * 32 + nt * 8 + g;
#pragma unroll
        for (int ks = 0; ks < 8; ks++) {
            const int r = 16 * ks + 2 * c;
            Wf[nt][ks][0] = pack_h2(__ldg(W2 + r * 64 + n),       __ldg(W2 + (r + 1) * 64 + n));
            Wf[nt][ks][1] = pack_h2(__ldg(W2 + (r + 8) * 64 + n), __ldg(W2 + (r + 9) * 64 + n));
        }
    }

    const int ustart = (int)(((long long)blockIdx.x * NUNITS) / GRID_MAIN);
    const int uend   = (int)(((long long)(blockIdx.x + 1) * NUNITS) / GRID_MAIN);

    __half2 Qa01[8], Qa89[8], Qb01[8], Qb89[8];
    float mx[4][4];
    const __half2 hz = __float2half2_rn(0.f);
    int cur_it = -1;

#pragma unroll 1
    for (int u = ustart; u < uend; u++) {
        const int it = u >> 6;
        const int ju = u & 63;

        if (it != cur_it) {
            if (cur_it >= 0) {
                // flush running max for previous i-tile
                const int i0 = cur_it * 64 + mg * 16 + g;
#pragma unroll
                for (int nt = 0; nt < 4; nt++) {
                    const int col = nh * 32 + nt * 8 + 2 * c;
                    atomicMax(&g_amax[i0 * 64 + col],           fkey(mx[nt][0]));
                    atomicMax(&g_amax[i0 * 64 + col + 1],       fkey(mx[nt][1]));
                    atomicMax(&g_amax[(i0 + 8) * 64 + col],     fkey(mx[nt][2]));
                    atomicMax(&g_amax[(i0 + 8) * 64 + col + 1], fkey(mx[nt][3]));
                }
            }
            cur_it = it;
            const int row0 = it * 64 + mg * 16 + g;
            const __half* q0 = g_Qh + row0 * 128;
            const __half* q1 = g_Qh + (row0 + 8) * 128;
#pragma unroll
            for (int ks = 0; ks < 8; ks++) {
                Qa01[ks] = *(const __half2*)(q0 + 16 * ks + 2 * c);
                Qa89[ks] = *(const __half2*)(q0 + 16 * ks + 2 * c + 8);
                Qb01[ks] = *(const __half2*)(q1 + 16 * ks + 2 * c);
                Qb89[ks] = *(const __half2*)(q1 + 16 * ks + 2 * c + 8);
            }
#pragma unroll
            for (int nt = 0; nt < 4; nt++)
#pragma unroll
                for (int r = 0; r < 4; r++) mx[nt][r] = -CUDART_INF_F;
        }

        const int jb = ju * 16;
#pragma unroll 1
        for (int jj = 0; jj < 16; jj += 2) {
            // Load two U rows (independent streams for ILP)
            __half2 U0[16], U1[16];
            const __half* r0 = g_Uh + (jb + jj) * 128;
            const __half* r1 = r0 + 128;
#pragma unroll
            for (int ks = 0; ks < 8; ks++) {
                U0[2*ks+0] = *(const __half2*)(r0 + 16 * ks + 2 * c);
                U0[2*ks+1] = *(const __half2*)(r0 + 16 * ks + 2 * c + 8);
                U1[2*ks+0] = *(const __half2*)(r1 + 16 * ks + 2 * c);
                U1[2*ks+1] = *(const __half2*)(r1 + 16 * ks + 2 * c + 8);
            }

            float d0[4][4], d1[4][4];
#pragma unroll
            for (int nt = 0; nt < 4; nt++)
#pragma unroll
                for (int r = 0; r < 4; r++) { d0[nt][r] = 0.f; d1[nt][r] = 0.f; }

#pragma unroll
            for (int ks = 0; ks < 8; ks++) {
                const uint32_t x0 = h2u(__hmax2(__hsub2(U0[2*ks+0], Qa01[ks]), hz));
                const uint32_t x1 = h2u(__hmax2(__hsub2(U0[2*ks+0], Qb01[ks]), hz));
                const uint32_t x2 = h2u(__hmax2(__hsub2(U0[2*ks+1], Qa89[ks]), hz));
                const uint32_t x3 = h2u(__hmax2(__hsub2(U0[2*ks+1], Qb89[ks]), hz));
                const uint32_t y0 = h2u(__hmax2(__hsub2(U1[2*ks+0], Qa01[ks]), hz));
                const uint32_t y1 = h2u(__hmax2(__hsub2(U1[2*ks+0], Qb01[ks]), hz));
                const uint32_t y2 = h2u(__hmax2(__hsub2(U1[2*ks+1], Qa89[ks]), hz));
                const uint32_t y3 = h2u(__hmax2(__hsub2(U1[2*ks+1], Qb89[ks]), hz));
#pragma unroll
                for (int nt = 0; nt < 4; nt++) {
                    mma_f16(d0[nt], x0, x1, x2, x3, Wf[nt][ks][0], Wf[nt][ks][1]);
                    mma_f16(d1[nt], y0, y1, y2, y3, Wf[nt][ks][0], Wf[nt][ks][1]);
                }
            }

#pragma unroll
            for (int nt = 0; nt < 4; nt++) {
                mx[nt][0] = fmaxf(mx[nt][0], fmaxf(d0[nt][0], d1[nt][0]));
                mx[nt][1] = fmaxf(mx[nt][1], fmaxf(d0[nt][1], d1[nt][1]));
                mx[nt][2] = fmaxf(mx[nt][2], fmaxf(d0[nt][2], d1[nt][2]));
                mx[nt][3] = fmaxf(mx[nt][3], fmaxf(d0[nt][3], d1[nt][3]));
            }
        }
    }

    // final flush
    if (cur_it >= 0) {
        const int i0 = cur_it * 64 + mg * 16 + g;
#pragma unroll
        for (int nt = 0; nt < 4; nt++) {
            const int col = nh * 32 + nt * 8 + 2 * c;
            atomicMax(&g_amax[i0 * 64 + col],           fkey(mx[nt][0]));
            atomicMax(&g_amax[i0 * 64 + col + 1],       fkey(mx[nt][1]));
            atomicMax(&g_amax[(i0 + 8) * 64 + col],     fkey(mx[nt][2]));
            atomicMax(&g_amax[(i0 + 8) * 64 + col + 1], fkey(mx[nt][3]));
        }
    }
}

// ---------------- Kernel 3: unmap + relu(+b2) ----------------
__global__ void combine_kernel(const float* __restrict__ b2, float* __restrict__ out) {
    int idx = blockIdx.x * 256 + threadIdx.x;  // i*64+n
    int n = idx & 63;
    float m = funkey(g_amax[idx]);
    out[idx] = fmaxf(m + b2[n], 0.f);
}

extern "C" void kernel_launch(void* const* d_in, const int* in_sizes, int n_in,
                              void* d_out, int out_size) {
    const float* hidden = (const float*)d_in[0];
    const float* track  = (const float*)d_in[1];
    const float* W_e    = (const float*)d_in[2];
    const float* b_e    = (const float*)d_in[3];
    const float* W1     = (const float*)d_in[4];
    const float* b1     = (const float*)d_in[5];
    const float* W2     = (const float*)d_in[6];
    const float* b2     = (const float*)d_in[7];
    float* out = (float*)d_out;

    precompute_kernel<<<NAG, 128>>>(hidden, track, W_e, b_e, W1, b1);
    main_kernel<<<GRID_MAIN, THREADS>>>(W2);
    combine_kernel<<<NAG * 64 / 256, 256>>>(b2, out);
}

// round 14
// speedup vs baseline: 1.1635x; 1.1635x over previous
#include <cuda_runtime.h>
#include <cuda_fp16.h>
#include <cstdint>
#include <math_constants.h>

#define NAG 1024
#define THREADS 256
#define GRID_MAIN 148
#define NUNITS 1024          // 16 i-tiles x 64 j-subchunks(16 j each)

__device__ __half g_Uh[NAG * 128];
__device__ __half g_Qh[NAG * 128];
__device__ unsigned int g_amax[NAG * 64];   // monotone-mapped f32 max keys

// ---------------- helpers ----------------
__device__ __forceinline__ uint32_t pack_h2(float lo, float hi) {
    uint32_t r;
    asm("cvt.rn.f16x2.f32 %0, %1, %2;" : "=r"(r) : "f"(hi), "f"(lo));
    return r;
}
__device__ __forceinline__ uint32_t h2u(__half2 h) {
    return *reinterpret_cast<uint32_t*>(&h);
}
// order-preserving f32 -> u32 (init 0 acts as -inf: any finite key > 0)
__device__ __forceinline__ unsigned int fkey(float f) {
    unsigned int b = __float_as_uint(f);
    return (b & 0x80000000u) ? ~b : (b | 0x80000000u);
}
__device__ __forceinline__ float funkey(unsigned int k) {
    return (k & 0x80000000u) ? __uint_as_float(k ^ 0x80000000u)
                             : __uint_as_float(~k);
}

// mma.sync m16n8k16 f16, f32 accum
__device__ __forceinline__ void mma_f16(float* d,
                                        uint32_t a0, uint32_t a1, uint32_t a2, uint32_t a3,
                                        uint32_t b0, uint32_t b1) {
    asm volatile(
        "mma.sync.aligned.m16n8k16.row.col.f32.f16.f16.f32 "
        "{%0,%1,%2,%3}, {%4,%5,%6,%7}, {%8,%9}, {%0,%1,%2,%3};"
        : "+f"(d[0]), "+f"(d[1]), "+f"(d[2]), "+f"(d[3])
        : "r"(a0), "r"(a1), "r"(a2), "r"(a3), "r"(b0), "r"(b1));
}

// ---------------- Kernel 1: precompute U, Q (fp16), 2 agents/block ----------------
__global__ void precompute_kernel(const float* __restrict__ hidden,
                                  const float* __restrict__ track,
                                  const float* __restrict__ W_e,
                                  const float* __restrict__ b_e,
                                  const float* __restrict__ W1,
                                  const float* __restrict__ b1) {
    __shared__ float sh[2][64];
    __shared__ float sP[2][16];
    const int a0 = blockIdx.x * 2;
    const int m = threadIdx.x;  // 0..127
    if (m < 64) {
        sh[0][m] = hidden[a0 * 64 + m];
        sh[1][m] = hidden[(a0 + 1) * 64 + m];
    }
    if (m < 16) {
#pragma unroll
        for (int q = 0; q < 2; q++) {
            float e0 = track[(a0 + q) * 16 + 14];
            float e1 = track[(a0 + q) * 16 + 15];
            sP[q][m] = e0 * W_e[m] + e1 * W_e[16 + m];
        }
    }
    // zero the atomic-max buffer (64K entries over 512 blocks x 128 thr)
    g_amax[blockIdx.x * 128 + m] = 0u;
    __syncthreads();
    const float bias = b1[m];
    float acc0 = bias, acc1 = bias, q0 = 0.f, q1 = 0.f;
#pragma unroll 8
    for (int h = 0; h < 64; h++) {
        const float w = W1[h * 128 + m];
        acc0 = fmaf(sh[0][h], w, acc0);
        acc1 = fmaf(sh[1][h], w, acc1);
    }
#pragma unroll
    for (int e = 0; e < 16; e++) {
        const float w = W1[(64 + e) * 128 + m];
        const float bw = b_e[e] * w;
        q0 = fmaf(sP[0][e], w, q0);
        q1 = fmaf(sP[1][e], w, q1);
        acc0 += bw; acc1 += bw;
    }
    g_Qh[a0 * 128 + m]       = __float2half_rn(q0);
    g_Uh[a0 * 128 + m]       = __float2half_rn(acc0 + q0);
    g_Qh[(a0 + 1) * 128 + m] = __float2half_rn(q1);
    g_Uh[(a0 + 1) * 128 + m] = __float2half_rn(acc1 + q1);
}

// ---------------- U row load ----------------
__device__ __forceinline__ void load_urow(__half2* Uv, const __half* Ur, int c) {
#pragma unroll
    for (int ks = 0; ks < 8; ks++) {
        Uv[2*ks+0] = *(const __half2*)(Ur + 16 * ks + 2 * c);
        Uv[2*ks+1] = *(const __half2*)(Ur + 16 * ks + 2 * c + 8);
    }
}

// ---------------- build + 4x MMA + running max for one j from buffer Uv ----------------
__device__ __forceinline__ void do_iter(const __half2* Uv,
                                        const __half2* Qa01, const __half2* Qa89,
                                        const __half2* Qb01, const __half2* Qb89,
                                        const uint32_t Wf[4][8][2],
                                        float mx[4][4], __half2 hz) {
    float d[4][4];
#pragma unroll
    for (int nt = 0; nt < 4; nt++)
#pragma unroll
        for (int r = 0; r < 4; r++) d[nt][r] = 0.f;
#pragma unroll
    for (int ks = 0; ks < 8; ks++) {
        const uint32_t a0 = h2u(__hmax2(__hsub2(Uv[2*ks+0], Qa01[ks]), hz));
        const uint32_t a1 = h2u(__hmax2(__hsub2(Uv[2*ks+0], Qb01[ks]), hz));
        const uint32_t a2 = h2u(__hmax2(__hsub2(Uv[2*ks+1], Qa89[ks]), hz));
        const uint32_t a3 = h2u(__hmax2(__hsub2(Uv[2*ks+1], Qb89[ks]), hz));
#pragma unroll
        for (int nt = 0; nt < 4; nt++)
            mma_f16(d[nt], a0, a1, a2, a3, Wf[nt][ks][0], Wf[nt][ks][1]);
    }
#pragma unroll
    for (int nt = 0; nt < 4; nt++) {
        mx[nt][0] = fmaxf(mx[nt][0], d[nt][0]);
        mx[nt][1] = fmaxf(mx[nt][1], d[nt][1]);
        mx[nt][2] = fmaxf(mx[nt][2], d[nt][2]);
        mx[nt][3] = fmaxf(mx[nt][3], d[nt][3]);
    }
}

// ---------------- Kernel 2: persistent, ping-pong U prefetch, atomic max ----------------
__global__ void __launch_bounds__(THREADS, 1)
main_kernel(const float* __restrict__ W2) {
    const int tid  = threadIdx.x;
    const int wid  = tid >> 5;
    const int lane = tid & 31;
    const int g = lane >> 2;
    const int c = lane & 3;
    const int mg = wid >> 1;
    const int nh = wid & 1;

    // W2 fragments (f16x2), invariant.
    uint32_t Wf[4][8][2];
#pragma unroll
    for (int nt = 0; nt < 4; nt++) {
        const int n = nh * 32 + nt * 8 + g;
#pragma unroll
        for (int ks = 0; ks < 8; ks++) {
            const int r = 16 * ks + 2 * c;
            Wf[nt][ks][0] = pack_h2(__ldg(W2 + r * 64 + n),       __ldg(W2 + (r + 1) * 64 + n));
            Wf[nt][ks][1] = pack_h2(__ldg(W2 + (r + 8) * 64 + n), __ldg(W2 + (r + 9) * 64 + n));
        }
    }

    const int ustart = (int)(((long long)blockIdx.x * NUNITS) / GRID_MAIN);
    const int uend   = (int)(((long long)(blockIdx.x + 1) * NUNITS) / GRID_MAIN);

    const __half2 hz = __float2half2_rn(0.f);
    __half2 Qa01[8], Qa89[8], Qb01[8], Qb89[8];
    __half2 UA[16], UB[16];
    float mx[4][4];

    int u = ustart;
#pragma unroll 1
    while (u < uend) {
        const int it = u >> 6;
        const int seg_end = min(uend, (it + 1) << 6);
        const int j0 = (u & 63) * 16;
        const int j1 = j0 + (seg_end - u) * 16;      // contiguous j range, multiple of 16

        // Q for this i-tile
        const int row0 = it * 64 + mg * 16 + g;
        {
            const __half* q0 = g_Qh + row0 * 128;
            const __half* q1 = g_Qh + (row0 + 8) * 128;
#pragma unroll
            for (int ks = 0; ks < 8; ks++) {
                Qa01[ks] = *(const __half2*)(q0 + 16 * ks + 2 * c);
                Qa89[ks] = *(const __half2*)(q0 + 16 * ks + 2 * c + 8);
                Qb01[ks] = *(const __half2*)(q1 + 16 * ks + 2 * c);
                Qb89[ks] = *(const __half2*)(q1 + 16 * ks + 2 * c + 8);
            }
        }
#pragma unroll
        for (int nt = 0; nt < 4; nt++)
#pragma unroll
            for (int r = 0; r < 4; r++) mx[nt][r] = -CUDART_INF_F;

        // prime buffer A with j0
        load_urow(UA, g_Uh + j0 * 128, c);

#pragma unroll 1
        for (int j = j0; j < j1; j += 2) {
            // prefetch j+1 into B, then consume A
            const int jn1 = min(j + 1, NAG - 1);
            load_urow(UB, g_Uh + jn1 * 128, c);
            do_iter(UA, Qa01, Qa89, Qb01, Qb89, Wf, mx, hz);
            // prefetch j+2 into A, then consume B
            const int jn2 = min(j + 2, NAG - 1);
            load_urow(UA, g_Uh + jn2 * 128, c);
            do_iter(UB, Qa01, Qa89, Qb01, Qb89, Wf, mx, hz);
        }

        // flush running max for this i-tile segment
#pragma unroll
        for (int nt = 0; nt < 4; nt++) {
            const int col = nh * 32 + nt * 8 + 2 * c;
            atomicMax(&g_amax[row0 * 64 + col],           fkey(mx[nt][0]));
            atomicMax(&g_amax[row0 * 64 + col + 1],       fkey(mx[nt][1]));
            atomicMax(&g_amax[(row0 + 8) * 64 + col],     fkey(mx[nt][2]));
            atomicMax(&g_amax[(row0 + 8) * 64 + col + 1], fkey(mx[nt][3]));
        }
        u = seg_end;
    }
}

// ---------------- Kernel 3: unmap + relu(+b2) ----------------
__global__ void combine_kernel(const float* __restrict__ b2, float* __restrict__ out) {
    int idx = blockIdx.x * 256 + threadIdx.x;  // i*64+n
    int n = idx & 63;
    float m = funkey(g_amax[idx]);
    out[idx] = fmaxf(m + b2[n], 0.f);
}

extern "C" void kernel_launch(void* const* d_in, const int* in_sizes, int n_in,
                              void* d_out, int out_size) {
    const float* hidden = (const float*)d_in[0];
    const float* track  = (const float*)d_in[1];
    const float* W_e    = (const float*)d_in[2];
    const float* b_e    = (const float*)d_in[3];
    const float* W1     = (const float*)d_in[4];
    const float* b1     = (const float*)d_in[5];
    const float* W2     = (const float*)d_in[6];
    const float* b2     = (const float*)d_in[7];
    float* out = (float*)d_out;

    precompute_kernel<<<NAG / 2, 128>>>(hidden, track, W_e, b_e, W1, b1);
    main_kernel<<<GRID_MAIN, THREADS>>>(W2);
    combine_kernel<<<NAG * 64 / 256, 256>>>(b2, out);
}